// round 2
// baseline (speedup 1.0000x reference)
#include <cuda_runtime.h>
#include <cstdint>

// Problem constants (fixed by the dataset)
#define NB   32    // num 4x4 blocks
#define BS   4
#define DIM  128   // NB*BS
#define NREL 16    // relations (blocks[16] = self-loop)

// ---------------------------------------------------------------------------
// Self-loop kernel: one warp per node, lane b handles block b (4 outputs).
// Also serves as the d_out initializer (out is poisoned before timing).
// out[n] = mask[n] ? xb[n] . blocks[NREL] : 0
// NOTE: node_keep_mask is a bool array serialized as int32 (4 bytes/elem).
// ---------------------------------------------------------------------------
__global__ __launch_bounds__(256) void self_kernel(
    const float* __restrict__ x,
    const int*   __restrict__ mask,     // int32 bool
    const float* __restrict__ blocks,
    float* __restrict__ out,
    int n_nodes)
{
    int gw   = (blockIdx.x * blockDim.x + threadIdx.x) >> 5;
    int lane = threadIdx.x & 31;
    if (gw >= n_nodes) return;
    const int n = gw;

    float4 o = make_float4(0.f, 0.f, 0.f, 0.f);
    if (__ldg(mask + n) != 0) {
        float4 xi = __ldg((const float4*)(x + (size_t)n * DIM) + lane);
        // block weights for relation NREL (self), block = lane: 16 floats
        const float4* W = (const float4*)blocks + ((size_t)NREL * NB + lane) * 4;
        float4 w0 = __ldg(W + 0);
        float4 w1 = __ldg(W + 1);
        float4 w2 = __ldg(W + 2);
        float4 w3 = __ldg(W + 3);
        // out_j = sum_i x_i * W[i][j]
        o.x = xi.x * w0.x + xi.y * w1.x + xi.z * w2.x + xi.w * w3.x;
        o.y = xi.x * w0.y + xi.y * w1.y + xi.z * w2.y + xi.w * w3.y;
        o.z = xi.x * w0.z + xi.y * w1.z + xi.z * w2.z + xi.w * w3.z;
        o.w = xi.x * w0.w + xi.y * w1.w + xi.z * w2.w + xi.w * w3.w;
    }
    *((float4*)(out + (size_t)n * DIM) + lane) = o;
}

// ---------------------------------------------------------------------------
// Edge kernel: one warp per DIRECTED edge (2E total: forward then reversed).
// lane b: gathers x[src] block b (float4, coalesced 512B/warp), multiplies by
// blocks[et][b] (4x4, hot in L1), scales by edge weight, and scatter-adds the
// 4 outputs with a single red.global.add.v4.f32 (no return, 16B aligned).
// ---------------------------------------------------------------------------
__global__ __launch_bounds__(256) void edge_kernel(
    const float* __restrict__ x,
    const int*   __restrict__ src,
    const int*   __restrict__ tgt,
    const int*   __restrict__ et,
    const float* __restrict__ ew,
    const float* __restrict__ blocks,
    float* __restrict__ out,
    int n_edges)
{
    int gw   = (blockIdx.x * blockDim.x + threadIdx.x) >> 5;
    int lane = threadIdx.x & 31;
    if (gw >= 2 * n_edges) return;

    const bool fwd = (gw < n_edges);
    const int  e   = fwd ? gw : gw - n_edges;

    const int   s = fwd ? __ldg(src + e) : __ldg(tgt + e);
    const int   t = fwd ? __ldg(tgt + e) : __ldg(src + e);
    const int   r = __ldg(et + e);
    const float w = __ldg(ew + e);

    float4 xi = __ldg((const float4*)(x + (size_t)s * DIM) + lane);

    const float4* W = (const float4*)blocks + ((size_t)r * NB + lane) * 4;
    float4 w0 = __ldg(W + 0);
    float4 w1 = __ldg(W + 1);
    float4 w2 = __ldg(W + 2);
    float4 w3 = __ldg(W + 3);

    float4 o;
    o.x = (xi.x * w0.x + xi.y * w1.x + xi.z * w2.x + xi.w * w3.x) * w;
    o.y = (xi.x * w0.y + xi.y * w1.y + xi.z * w2.y + xi.w * w3.y) * w;
    o.z = (xi.x * w0.z + xi.y * w1.z + xi.z * w2.z + xi.w * w3.z) * w;
    o.w = (xi.x * w0.w + xi.y * w1.w + xi.z * w2.w + xi.w * w3.w) * w;

    float* dst = out + (size_t)t * DIM + lane * 4;   // 16B aligned
    asm volatile("red.global.add.v4.f32 [%0], {%1, %2, %3, %4};"
                 :: "l"(dst), "f"(o.x), "f"(o.y), "f"(o.z), "f"(o.w)
                 : "memory");
}

// ---------------------------------------------------------------------------
// Launch
// Inputs (metadata order):
//   0: x              float32 (10000*128)
//   1: node_keep_mask int32   (10000)     [bool serialized as int32]
//   2: source         int32   (160000)
//   3: target         int32   (160000)
//   4: edge_type      int32   (160000)
//   5: edge_weights   float32 (160000)
//   6: blocks         float32 (17*32*4*4)
// Output: float32 (10000*128)
// ---------------------------------------------------------------------------
extern "C" void kernel_launch(void* const* d_in, const int* in_sizes, int n_in,
                              void* d_out, int out_size)
{
    const float* x      = (const float*)d_in[0];
    const int*   mask   = (const int*)d_in[1];
    const int*   src    = (const int*)d_in[2];
    const int*   tgt    = (const int*)d_in[3];
    const int*   et     = (const int*)d_in[4];
    const float* ew     = (const float*)d_in[5];
    const float* blocks = (const float*)d_in[6];
    float*       out    = (float*)d_out;

    const int n_nodes = in_sizes[1];
    const int n_edges = in_sizes[2];

    // Self-loop + output init: one warp per node
    {
        int warps   = n_nodes;
        int threads = 256;
        int blocks_ = (warps * 32 + threads - 1) / threads;
        self_kernel<<<blocks_, threads>>>(x, mask, blocks, out, n_nodes);
    }

    // Edge messages: one warp per directed edge (2E)
    {
        int warps   = 2 * n_edges;
        int threads = 256;
        int blocks_ = (warps * 32 + threads - 1) / threads;
        edge_kernel<<<blocks_, threads>>>(x, src, tgt, et, ew, blocks, out, n_edges);
    }
}

// round 3
// speedup vs baseline: 1.0024x; 1.0024x over previous
#include <cuda_runtime.h>
#include <cstdint>

#define NB   32    // num 4x4 blocks
#define BS   4
#define DIM  128   // NB*BS
#define NREL 16    // edge relations (blocks[16] = self-loop)

// ---------------------------------------------------------------------------
// Self-loop kernel: one warp per node, lane b handles block b (4 outputs).
// Also initializes d_out (poisoned before timing).
// node_keep_mask is bool serialized as int32.
// ---------------------------------------------------------------------------
__global__ __launch_bounds__(256) void self_kernel(
    const float* __restrict__ x,
    const int*   __restrict__ mask,
    const float* __restrict__ blocks,
    float* __restrict__ out,
    int n_nodes)
{
    int gw   = (blockIdx.x * blockDim.x + threadIdx.x) >> 5;
    int lane = threadIdx.x & 31;
    if (gw >= n_nodes) return;
    const int n = gw;

    float4 o = make_float4(0.f, 0.f, 0.f, 0.f);
    if (__ldg(mask + n) != 0) {
        float4 xi = __ldg((const float4*)(x + (size_t)n * DIM) + lane);
        const float4* W = (const float4*)blocks + ((size_t)NREL * NB + lane) * 4;
        float4 w0 = __ldg(W + 0);
        float4 w1 = __ldg(W + 1);
        float4 w2 = __ldg(W + 2);
        float4 w3 = __ldg(W + 3);
        o.x = xi.x * w0.x + xi.y * w1.x + xi.z * w2.x + xi.w * w3.x;
        o.y = xi.x * w0.y + xi.y * w1.y + xi.z * w2.y + xi.w * w3.y;
        o.z = xi.x * w0.z + xi.y * w1.z + xi.z * w2.z + xi.w * w3.z;
        o.w = xi.x * w0.w + xi.y * w1.w + xi.z * w2.w + xi.w * w3.w;
    }
    *((float4*)(out + (size_t)n * DIM) + lane) = o;
}

// ---------------------------------------------------------------------------
// Edge kernel: grid-stride, one warp per DIRECTED edge per iteration.
// Weights for all 16 edge relations cached in shared memory (32KB);
// lane b does block b's 4x4 GEMV from smem, gathers x[src] (coalesced
// LDG.128), scatter-adds via red.global.add.v4.f32. 2x unrolled for MLP.
// ---------------------------------------------------------------------------
#define EDGE_THREADS 512
#define EDGE_CTAS    592   // 4 per SM on 148 SMs

__global__ __launch_bounds__(EDGE_THREADS) void edge_kernel(
    const float* __restrict__ x,
    const int*   __restrict__ src,
    const int*   __restrict__ tgt,
    const int*   __restrict__ et,
    const float* __restrict__ ew,
    const float* __restrict__ blocks,
    float* __restrict__ out,
    int n_edges)
{
    // smem copy of edge-relation weights: [16][32][4][4] floats = 2048 float4
    __shared__ float4 sW[NREL * NB * 4];
    for (int i = threadIdx.x; i < NREL * NB * 4; i += EDGE_THREADS)
        sW[i] = __ldg((const float4*)blocks + i);
    __syncthreads();

    const int lane = threadIdx.x & 31;
    const int warp = (blockIdx.x * EDGE_THREADS + threadIdx.x) >> 5;
    const int nw   = (gridDim.x * EDGE_THREADS) >> 5;
    const int E2   = 2 * n_edges;

    int d = warp;
    // 2x unrolled main loop
    for (; d + nw < E2; d += 2 * nw) {
        const int d0 = d, d1 = d + nw;

        const bool f0 = (d0 < n_edges);
        const int  e0 = f0 ? d0 : d0 - n_edges;
        const bool f1 = (d1 < n_edges);
        const int  e1 = f1 ? d1 : d1 - n_edges;

        const int   s0 = __ldg(f0 ? src + e0 : tgt + e0);
        const int   t0 = __ldg(f0 ? tgt + e0 : src + e0);
        const int   r0 = __ldg(et + e0);
        const float w0_ = __ldg(ew + e0);

        const int   s1 = __ldg(f1 ? src + e1 : tgt + e1);
        const int   t1 = __ldg(f1 ? tgt + e1 : src + e1);
        const int   r1 = __ldg(et + e1);
        const float w1_ = __ldg(ew + e1);

        float4 xa = __ldg((const float4*)(x + (size_t)s0 * DIM) + lane);
        float4 xb = __ldg((const float4*)(x + (size_t)s1 * DIM) + lane);

        const float4* Wa = sW + (r0 * (NB * 4) + lane * 4);
        const float4* Wb = sW + (r1 * (NB * 4) + lane * 4);
        float4 a0 = Wa[0], a1 = Wa[1], a2 = Wa[2], a3 = Wa[3];
        float4 b0 = Wb[0], b1 = Wb[1], b2 = Wb[2], b3 = Wb[3];

        float4 oa, ob;
        oa.x = (xa.x * a0.x + xa.y * a1.x + xa.z * a2.x + xa.w * a3.x) * w0_;
        oa.y = (xa.x * a0.y + xa.y * a1.y + xa.z * a2.y + xa.w * a3.y) * w0_;
        oa.z = (xa.x * a0.z + xa.y * a1.z + xa.z * a2.z + xa.w * a3.z) * w0_;
        oa.w = (xa.x * a0.w + xa.y * a1.w + xa.z * a2.w + xa.w * a3.w) * w0_;
        ob.x = (xb.x * b0.x + xb.y * b1.x + xb.z * b2.x + xb.w * b3.x) * w1_;
        ob.y = (xb.x * b0.y + xb.y * b1.y + xb.z * b2.y + xb.w * b3.y) * w1_;
        ob.z = (xb.x * b0.z + xb.y * b1.z + xb.z * b2.z + xb.w * b3.z) * w1_;
        ob.w = (xb.x * b0.w + xb.y * b1.w + xb.z * b2.w + xb.w * b3.w) * w1_;

        float* dst0 = out + (size_t)t0 * DIM + lane * 4;
        float* dst1 = out + (size_t)t1 * DIM + lane * 4;
        asm volatile("red.global.add.v4.f32 [%0], {%1, %2, %3, %4};"
                     :: "l"(dst0), "f"(oa.x), "f"(oa.y), "f"(oa.z), "f"(oa.w)
                     : "memory");
        asm volatile("red.global.add.v4.f32 [%0], {%1, %2, %3, %4};"
                     :: "l"(dst1), "f"(ob.x), "f"(ob.y), "f"(ob.z), "f"(ob.w)
                     : "memory");
    }
    // tail
    for (; d < E2; d += nw) {
        const bool fwd = (d < n_edges);
        const int  e   = fwd ? d : d - n_edges;
        const int   s = __ldg(fwd ? src + e : tgt + e);
        const int   t = __ldg(fwd ? tgt + e : src + e);
        const int   r = __ldg(et + e);
        const float w = __ldg(ew + e);

        float4 xi = __ldg((const float4*)(x + (size_t)s * DIM) + lane);
        const float4* W = sW + (r * (NB * 4) + lane * 4);
        float4 w0 = W[0], w1 = W[1], w2 = W[2], w3 = W[3];

        float4 o;
        o.x = (xi.x * w0.x + xi.y * w1.x + xi.z * w2.x + xi.w * w3.x) * w;
        o.y = (xi.x * w0.y + xi.y * w1.y + xi.z * w2.y + xi.w * w3.y) * w;
        o.z = (xi.x * w0.z + xi.y * w1.z + xi.z * w2.z + xi.w * w3.z) * w;
        o.w = (xi.x * w0.w + xi.y * w1.w + xi.z * w2.w + xi.w * w3.w) * w;

        float* dst = out + (size_t)t * DIM + lane * 4;
        asm volatile("red.global.add.v4.f32 [%0], {%1, %2, %3, %4};"
                     :: "l"(dst), "f"(o.x), "f"(o.y), "f"(o.z), "f"(o.w)
                     : "memory");
    }
}

// ---------------------------------------------------------------------------
// Inputs (metadata order):
//   0: x              float32 (10000*128)
//   1: node_keep_mask int32   (10000)
//   2: source         int32   (160000)
//   3: target         int32   (160000)
//   4: edge_type      int32   (160000)
//   5: edge_weights   float32 (160000)
//   6: blocks         float32 (17*32*4*4)
// Output: float32 (10000*128)
// ---------------------------------------------------------------------------
extern "C" void kernel_launch(void* const* d_in, const int* in_sizes, int n_in,
                              void* d_out, int out_size)
{
    const float* x      = (const float*)d_in[0];
    const int*   mask   = (const int*)d_in[1];
    const int*   src    = (const int*)d_in[2];
    const int*   tgt    = (const int*)d_in[3];
    const int*   et     = (const int*)d_in[4];
    const float* ew     = (const float*)d_in[5];
    const float* blocks = (const float*)d_in[6];
    float*       out    = (float*)d_out;

    const int n_nodes = in_sizes[1];
    const int n_edges = in_sizes[2];

    // Self-loop + output init
    {
        int threads = 256;
        int blocks_ = (n_nodes * 32 + threads - 1) / threads;
        self_kernel<<<blocks_, threads>>>(x, mask, blocks, out, n_nodes);
    }

    // Edge messages
    edge_kernel<<<EDGE_CTAS, EDGE_THREADS>>>(x, src, tgt, et, ew, blocks, out, n_edges);
}

// round 5
// speedup vs baseline: 1.7798x; 1.7756x over previous
#include <cuda_runtime.h>
#include <cstdint>

#define NB   32    // num 4x4 blocks
#define BS   4
#define DIM  128   // NB*BS
#define NREL 16    // edge relations (blocks[16] = self-loop)

// ---------------------------------------------------------------------------
// Self-loop kernel: one warp per node, lane b handles block b.
// Also initializes d_out (poisoned before timing). mask is int32-bool.
// ---------------------------------------------------------------------------
__global__ __launch_bounds__(256) void self_kernel(
    const float* __restrict__ x,
    const int*   __restrict__ mask,
    const float* __restrict__ blocks,
    float* __restrict__ out,
    int n_nodes)
{
    int gw   = (blockIdx.x * blockDim.x + threadIdx.x) >> 5;
    int lane = threadIdx.x & 31;
    if (gw >= n_nodes) return;
    const int n = gw;

    float4 o = make_float4(0.f, 0.f, 0.f, 0.f);
    if (__ldg(mask + n) != 0) {
        float4 xi = __ldg((const float4*)(x + (size_t)n * DIM) + lane);
        const float4* W = (const float4*)blocks + ((size_t)NREL * NB + lane) * 4;
        float4 w0 = __ldg(W + 0);
        float4 w1 = __ldg(W + 1);
        float4 w2 = __ldg(W + 2);
        float4 w3 = __ldg(W + 3);
        o.x = xi.x * w0.x + xi.y * w1.x + xi.z * w2.x + xi.w * w3.x;
        o.y = xi.x * w0.y + xi.y * w1.y + xi.z * w2.y + xi.w * w3.y;
        o.z = xi.x * w0.z + xi.y * w1.z + xi.z * w2.z + xi.w * w3.z;
        o.w = xi.x * w0.w + xi.y * w1.w + xi.z * w2.w + xi.w * w3.w;
    }
    *((float4*)(out + (size_t)n * DIM) + lane) = o;
}

// ---------------------------------------------------------------------------
// Edge kernel.
// smem W layout TRANSPOSED to [rel][row i][block] (float4 over j):
//   lane b reads sWt[r*128 + i*32 + b]  -> 32 consecutive float4 per warp
//   = 512B contiguous = conflict-free LDS.128 (4 phases, the minimum).
// Each warp owns a contiguous chunk of 32 directed edges: lanes load the
// 4 meta arrays coalesced once, then __shfl per edge. Scatter-add via
// red.global.add.v4.f32 (no return).
// ---------------------------------------------------------------------------
#define EDGE_THREADS 512
#define EDGE_CTAS    444   // 3 CTAs/SM (regs 40 x 1536 thr fits 64K RF)

__global__ __launch_bounds__(EDGE_THREADS) void edge_kernel(
    const float* __restrict__ x,
    const int*   __restrict__ src,
    const int*   __restrict__ tgt,
    const int*   __restrict__ et,
    const float* __restrict__ ew,
    const float* __restrict__ blocks,
    float* __restrict__ out,
    int n_edges)
{
    // Transposed weights: sWt[r][i][b] = blocks[r][b][i][:]  (float4 over j)
    __shared__ float4 sWt[NREL * 4 * NB];   // 2048 float4 = 32KB
    for (int idx = threadIdx.x; idx < NREL * 4 * NB; idx += EDGE_THREADS) {
        int b = idx & 31;
        int i = (idx >> 5) & 3;
        int r = idx >> 7;
        sWt[idx] = __ldg((const float4*)blocks + (r * 128 + b * 4 + i));
    }
    __syncthreads();

    const int lane = threadIdx.x & 31;
    const int warp = (blockIdx.x * EDGE_THREADS + threadIdx.x) >> 5;
    const int nw   = (gridDim.x * EDGE_THREADS) >> 5;
    const int E2   = 2 * n_edges;
    const int nchunks = (E2 + 31) >> 5;

    for (int c = warp; c < nchunks; c += nw) {
        const int base = c << 5;
        const int cnt  = min(32, E2 - base);

        // Coalesced meta load: lane l handles directed edge base+l
        int   s_l = 0, t_l = 0, r_l = 0;
        float w_l = 0.f;
        {
            int d = base + lane;
            if (lane < cnt) {
                bool fwd = (d < n_edges);
                int  e   = fwd ? d : d - n_edges;
                s_l = __ldg(fwd ? src + e : tgt + e);
                t_l = __ldg(fwd ? tgt + e : src + e);
                r_l = __ldg(et + e);
                w_l = __ldg(ew + e);
            }
        }

        #pragma unroll 4
        for (int k = 0; k < cnt; k++) {
            const int   s = __shfl_sync(0xffffffffu, s_l, k);
            const int   t = __shfl_sync(0xffffffffu, t_l, k);
            const int   r = __shfl_sync(0xffffffffu, r_l, k);
            const float w = __shfl_sync(0xffffffffu, w_l, k);

            float4 xi = __ldg((const float4*)(x + (size_t)s * DIM) + lane);

            const float4* W = sWt + r * 128 + lane;   // + i*32 per row
            float4 w0 = W[0];
            float4 w1 = W[32];
            float4 w2 = W[64];
            float4 w3 = W[96];

            float4 o;
            o.x = (xi.x * w0.x + xi.y * w1.x + xi.z * w2.x + xi.w * w3.x) * w;
            o.y = (xi.x * w0.y + xi.y * w1.y + xi.z * w2.y + xi.w * w3.y) * w;
            o.z = (xi.x * w0.z + xi.y * w1.z + xi.z * w2.z + xi.w * w3.z) * w;
            o.w = (xi.x * w0.w + xi.y * w1.w + xi.z * w2.w + xi.w * w3.w) * w;

            float* dst = out + (size_t)t * DIM + lane * 4;   // 16B aligned
            asm volatile("red.global.add.v4.f32 [%0], {%1, %2, %3, %4};"
                         :: "l"(dst), "f"(o.x), "f"(o.y), "f"(o.z), "f"(o.w));
        }
    }
}

// ---------------------------------------------------------------------------
// Inputs (metadata order):
//   0: x              float32 (10000*128)
//   1: node_keep_mask int32   (10000)
//   2: source         int32   (160000)
//   3: target         int32   (160000)
//   4: edge_type      int32   (160000)
//   5: edge_weights   float32 (160000)
//   6: blocks         float32 (17*32*4*4)
// Output: float32 (10000*128)
// ---------------------------------------------------------------------------
extern "C" void kernel_launch(void* const* d_in, const int* in_sizes, int n_in,
                              void* d_out, int out_size)
{
    const float* x      = (const float*)d_in[0];
    const int*   mask   = (const int*)d_in[1];
    const int*   src    = (const int*)d_in[2];
    const int*   tgt    = (const int*)d_in[3];
    const int*   et     = (const int*)d_in[4];
    const float* ew     = (const float*)d_in[5];
    const float* blocks = (const float*)d_in[6];
    float*       out    = (float*)d_out;

    const int n_nodes = in_sizes[1];
    const int n_edges = in_sizes[2];

    // Self-loop + output init
    {
        int threads = 256;
        int blocks_ = (n_nodes * 32 + threads - 1) / threads;
        self_kernel<<<blocks_, threads>>>(x, mask, blocks, out, n_nodes);
    }

    // Edge messages
    edge_kernel<<<EDGE_CTAS, EDGE_THREADS>>>(x, src, tgt, et, ew, blocks, out, n_edges);
}